// round 7
// baseline (speedup 1.0000x reference)
#include <cuda_runtime.h>

#define B_   16
#define C_   384
#define H_   56
#define W_   56
#define HW_  3136
#define NHW_ 50176
#define TOT_ 19267584
#define KL   31
#define PL   15
#define KS   5
#define TS   86        // 56 + 2*15
#define STR  87        // odd stride: consecutive rows -> distinct banks
#define WIDE 28        // output columns per thread
#define NTHR 224       // 2 images x (56 rows x 2 strips) -- every lane works
#define TILE_F (TS * STR)   // 7482 floats per image tile

// dynamic smem layout (floats): tile[2*TILE_F] | wl[2*961] | ws[2*25] | red[28]
#define WL_OFF  (2 * TILE_F)
#define WS_OFF  (WL_OFF + 2 * 961)
#define RED_OFF (WS_OFF + 2 * 25)
#define SMEM_FLOATS (RED_OFF + 28)
#define SMEM_BYTES  (SMEM_FLOATS * 4)

// Scratch (allocation-free contract: __device__ globals)
__device__ float g_yl[TOT_];
__device__ float g_ys[TOT_];
__device__ float g_acc[C_ * 4];   // per channel: sumL, sqL, sumS, sqS
__device__ float g_prm[C_ * 3];   // per channel: aL, aS, bias

__global__ void k_zero() {
    int i = blockIdx.x * blockDim.x + threadIdx.x;
    if (i < C_ * 4) g_acc[i] = 0.f;
}

__global__ __launch_bounds__(NTHR) void k_conv(const float* __restrict__ x,
                                               const float* __restrict__ wl_g,
                                               const float* __restrict__ ws_g) {
    extern __shared__ float sm[];
    float* tl  = sm;
    float* wl  = sm + WL_OFF;
    float* ws  = sm + WS_OFF;
    float* red = sm + RED_OFF;

    const int blk = blockIdx.x;          // p*C + c, p in [0,8)
    const int c   = blk % C_;
    const int p   = blk / C_;            // image pair index
    const int b0  = 2 * p;
    const int tid = threadIdx.x;

    // Load both padded tiles (zero halo of 15), row stride 87
    for (int idx = tid; idx < 2 * TS * TS; idx += NTHR) {
        int im = idx / (TS * TS);
        int k  = idx - im * (TS * TS);
        int r = k / TS, q = k - r * TS;
        int hy = r - PL, wx = q - PL;
        float v = 0.f;
        if (hy >= 0 && hy < H_ && wx >= 0 && wx < W_)
            v = x[((size_t)(b0 + im) * C_ + c) * HW_ + hy * W_ + wx];
        tl[im * TILE_F + r * STR + q] = v;
    }
    // Weights (same channel for both halves; duplicate per half for uniform addressing)
    for (int idx = tid; idx < 2 * KL * KL; idx += NTHR) {
        int im = idx / (KL * KL);
        int k  = idx - im * (KL * KL);
        wl[im * (KL * KL) + k] = wl_g[c * KL * KL + k];
    }
    if (tid < 2 * KS * KS) {
        int im = tid / (KS * KS);
        int k  = tid - im * (KS * KS);
        ws[im * (KS * KS) + k] = ws_g[c * KS * KS + k];
    }
    __syncthreads();

    const int half = tid / 112;          // which image of the pair
    const int lt   = tid - half * 112;   // 0..111
    const int row  = lt % 56;            // output row
    const int col0 = (lt / 56) * WIDE;   // 0 or 28

    const float* tile = tl + half * TILE_F;
    const float* wlh  = wl + half * (KL * KL);
    const float* wsh  = ws + half * (KS * KS);
    const size_t ob = ((size_t)(b0 + half) * C_ + c) * HW_ + (size_t)row * W_ + col0;

    float sL = 0.f, qL = 0.f, sS = 0.f, qS = 0.f;

    // ---- 31x31 depthwise conv, 28-wide rolling register window ----
    {
        float accL[WIDE];
        #pragma unroll
        for (int t = 0; t < WIDE; t++) accL[t] = 0.f;

        #pragma unroll 1
        for (int i = 0; i < KL; i++) {
            const float* xr = &tile[(row + i) * STR + col0];
            const float* wr = &wlh[i * KL];
            float xw[WIDE];
            #pragma unroll
            for (int t = 0; t < WIDE; t++) xw[t] = xr[t];
            #pragma unroll
            for (int j = 0; j < KL; j++) {
                const float wv = wr[j];
                #pragma unroll
                for (int t = 0; t < WIDE; t++)
                    accL[t] = fmaf(xw[(j + t) % WIDE], wv, accL[t]);
                if (j < KL - 1) xw[j % WIDE] = xr[j + WIDE];
            }
        }

        #pragma unroll
        for (int t = 0; t < WIDE; t += 4)
            *(float4*)&g_yl[ob + t] = make_float4(accL[t], accL[t+1], accL[t+2], accL[t+3]);
        #pragma unroll
        for (int t = 0; t < WIDE; t++) {
            sL += accL[t]; qL = fmaf(accL[t], accL[t], qL);
        }
    }

    // ---- 5x5 depthwise conv (pad 2): offset +13 in the 15-halo tile ----
    {
        float accS[WIDE];
        #pragma unroll
        for (int t = 0; t < WIDE; t++) accS[t] = 0.f;
        #pragma unroll 1
        for (int i = 0; i < KS; i++) {
            const float* xr = &tile[(row + i + 13) * STR + col0 + 13];
            const float* wr = &wsh[i * KS];
            float xv[WIDE + 4];
            #pragma unroll
            for (int t = 0; t < WIDE + 4; t++) xv[t] = xr[t];
            #pragma unroll
            for (int j = 0; j < KS; j++) {
                const float wv = wr[j];
                #pragma unroll
                for (int t = 0; t < WIDE; t++)
                    accS[t] = fmaf(xv[j + t], wv, accS[t]);
            }
        }

        #pragma unroll
        for (int t = 0; t < WIDE; t += 4)
            *(float4*)&g_ys[ob + t] = make_float4(accS[t], accS[t+1], accS[t+2], accS[t+3]);
        #pragma unroll
        for (int t = 0; t < WIDE; t++) {
            sS += accS[t]; qS = fmaf(accS[t], accS[t], qS);
        }
    }

    // ---- block reduction of the 4 stats (7 warps, all same channel) ----
    #pragma unroll
    for (int o = 16; o; o >>= 1) {
        sL += __shfl_down_sync(0xffffffffu, sL, o);
        qL += __shfl_down_sync(0xffffffffu, qL, o);
        sS += __shfl_down_sync(0xffffffffu, sS, o);
        qS += __shfl_down_sync(0xffffffffu, qS, o);
    }
    const int lane = tid & 31, wpid = tid >> 5;
    if (lane == 0) { red[wpid*4+0]=sL; red[wpid*4+1]=qL; red[wpid*4+2]=sS; red[wpid*4+3]=qS; }
    __syncthreads();
    if (tid < 4) {
        float v = 0.f;
        #pragma unroll
        for (int ww = 0; ww < 7; ww++) v += red[ww * 4 + tid];
        atomicAdd(&g_acc[c * 4 + tid], v);
    }
}

__global__ void k_stats(const float* __restrict__ gL, const float* __restrict__ bL,
                        const float* __restrict__ gS, const float* __restrict__ bS) {
    int c = blockIdx.x * blockDim.x + threadIdx.x;
    if (c >= C_) return;
    const float inv_n = 1.f / (float)NHW_;
    float mL = g_acc[c*4+0] * inv_n;
    float vL = g_acc[c*4+1] * inv_n - mL * mL;
    float aL = gL[c] * rsqrtf(vL + 1e-5f);
    float mS = g_acc[c*4+2] * inv_n;
    float vS = g_acc[c*4+3] * inv_n - mS * mS;
    float aS = gS[c] * rsqrtf(vS + 1e-5f);
    g_prm[c]        = aL;
    g_prm[C_ + c]   = aS;
    g_prm[2*C_ + c] = bL[c] - mL * aL + bS[c] - mS * aS;
}

__global__ __launch_bounds__(256) void k_out(float* __restrict__ out) {
    int i = blockIdx.x * blockDim.x + threadIdx.x;
    if (i >= TOT_ / 4) return;
    int e = i * 4;
    int c = (e / HW_) % C_;          // HW_ divisible by 4 -> channel constant in float4
    float aL = g_prm[c], aS = g_prm[C_ + c], bb = g_prm[2*C_ + c];
    float4 l = ((const float4*)g_yl)[i];
    float4 s = ((const float4*)g_ys)[i];
    float4 o;
    o.x = fmaf(aL, l.x, fmaf(aS, s.x, bb));
    o.y = fmaf(aL, l.y, fmaf(aS, s.y, bb));
    o.z = fmaf(aL, l.z, fmaf(aS, s.z, bb));
    o.w = fmaf(aL, l.w, fmaf(aS, s.w, bb));
    ((float4*)out)[i] = o;
}

extern "C" void kernel_launch(void* const* d_in, const int* in_sizes, int n_in,
                              void* d_out, int out_size) {
    const float* x  = (const float*)d_in[0];
    const float* wl = (const float*)d_in[1];
    const float* gl = (const float*)d_in[2];
    const float* bl = (const float*)d_in[3];
    const float* ws = (const float*)d_in[4];
    const float* gs = (const float*)d_in[5];
    const float* bs = (const float*)d_in[6];

    cudaFuncSetAttribute(k_conv, cudaFuncAttributeMaxDynamicSharedMemorySize, SMEM_BYTES);

    k_zero<<<6, 256>>>();
    k_conv<<<8 * C_, NTHR, SMEM_BYTES>>>(x, wl, ws);
    k_stats<<<2, 192>>>(gl, bl, gs, bs);
    k_out<<<(TOT_ / 4 + 255) / 256, 256>>>((float*)d_out);
}

// round 8
// speedup vs baseline: 1.0900x; 1.0900x over previous
#include <cuda_runtime.h>

#define B_   16
#define C_   384
#define H_   56
#define W_   56
#define HW_  3136
#define NHW_ 50176
#define TOT_ 19267584
#define KL   31
#define PL   15
#define KS   5
#define TS   86        // 56 + 2*15
#define STR  87        // odd stride: consecutive rows -> distinct banks
#define WIDE 14        // output columns per thread
#define NTHR 224       // 56 rows x 4 strips -- every lane works

// Scratch (allocation-free contract: __device__ globals)
__device__ float g_yl[TOT_];
__device__ float g_ys[TOT_];
__device__ float g_acc[C_ * 4];   // per channel: sumL, sqL, sumS, sqS
__device__ float g_prm[C_ * 3];   // per channel: aL, aS, bias

__global__ void k_zero() {
    int i = blockIdx.x * blockDim.x + threadIdx.x;
    if (i < C_ * 4) g_acc[i] = 0.f;
}

__global__ __launch_bounds__(NTHR) void k_conv(const float* __restrict__ x,
                                               const float* __restrict__ wl_g,
                                               const float* __restrict__ ws_g) {
    __shared__ float tile[TS * STR];
    __shared__ float wl[KL * KL];
    __shared__ float ws[KS * KS];
    __shared__ float red[7 * 4];

    const int blk = blockIdx.x;          // n*C + c
    const int c   = blk % C_;
    const int tid = threadIdx.x;
    const float* img = x + (size_t)blk * HW_;

    // Load padded tile (zero halo of 15), row stride 87
    for (int idx = tid; idx < TS * TS; idx += NTHR) {
        int r = idx / TS, q = idx - r * TS;
        int hy = r - PL, wx = q - PL;
        float v = 0.f;
        if (hy >= 0 && hy < H_ && wx >= 0 && wx < W_) v = img[hy * W_ + wx];
        tile[r * STR + q] = v;
    }
    for (int idx = tid; idx < KL * KL; idx += NTHR) wl[idx] = wl_g[c * KL * KL + idx];
    if (tid < KS * KS) ws[tid] = ws_g[c * KS * KS + tid];
    __syncthreads();

    const int row  = tid % 56;           // output row
    const int col0 = (tid / 56) * WIDE;  // 0, 14, 28, 42
    const size_t ob = (size_t)blk * HW_ + (size_t)row * W_ + col0;

    float sL = 0.f, qL = 0.f, sS = 0.f, qS = 0.f;

    // ---- 31x31 depthwise conv, 14-wide rolling register window ----
    {
        float accL[WIDE];
        #pragma unroll
        for (int t = 0; t < WIDE; t++) accL[t] = 0.f;

        #pragma unroll 1
        for (int i = 0; i < KL; i++) {
            const float* xr = &tile[(row + i) * STR + col0];
            const float* wr = &wl[i * KL];
            float xw[WIDE];
            #pragma unroll
            for (int t = 0; t < WIDE; t++) xw[t] = xr[t];
            #pragma unroll
            for (int j = 0; j < KL; j++) {
                const float wv = wr[j];
                #pragma unroll
                for (int t = 0; t < WIDE; t++)
                    accL[t] = fmaf(xw[(j + t) % WIDE], wv, accL[t]);
                if (j < KL - 1) xw[j % WIDE] = xr[j + WIDE];
            }
        }

        #pragma unroll
        for (int t = 0; t < WIDE; t += 2)
            *(float2*)&g_yl[ob + t] = make_float2(accL[t], accL[t+1]);
        #pragma unroll
        for (int t = 0; t < WIDE; t++) {
            sL += accL[t]; qL = fmaf(accL[t], accL[t], qL);
        }
    }

    // ---- 5x5 depthwise conv (pad 2): offset +13 in the 15-halo tile ----
    {
        float accS[WIDE];
        #pragma unroll
        for (int t = 0; t < WIDE; t++) accS[t] = 0.f;
        #pragma unroll 1
        for (int i = 0; i < KS; i++) {
            const float* xr = &tile[(row + i + 13) * STR + col0 + 13];
            const float* wr = &ws[i * KS];
            float xv[WIDE + 4];
            #pragma unroll
            for (int t = 0; t < WIDE + 4; t++) xv[t] = xr[t];
            #pragma unroll
            for (int j = 0; j < KS; j++) {
                const float wv = wr[j];
                #pragma unroll
                for (int t = 0; t < WIDE; t++)
                    accS[t] = fmaf(xv[j + t], wv, accS[t]);
            }
        }

        #pragma unroll
        for (int t = 0; t < WIDE; t += 2)
            *(float2*)&g_ys[ob + t] = make_float2(accS[t], accS[t+1]);
        #pragma unroll
        for (int t = 0; t < WIDE; t++) {
            sS += accS[t]; qS = fmaf(accS[t], accS[t], qS);
        }
    }

    // ---- block reduction of the 4 stats (7 warps) ----
    #pragma unroll
    for (int o = 16; o; o >>= 1) {
        sL += __shfl_down_sync(0xffffffffu, sL, o);
        qL += __shfl_down_sync(0xffffffffu, qL, o);
        sS += __shfl_down_sync(0xffffffffu, sS, o);
        qS += __shfl_down_sync(0xffffffffu, qS, o);
    }
    const int lane = tid & 31, wpid = tid >> 5;
    if (lane == 0) { red[wpid*4+0]=sL; red[wpid*4+1]=qL; red[wpid*4+2]=sS; red[wpid*4+3]=qS; }
    __syncthreads();
    if (tid < 4) {
        float v = 0.f;
        #pragma unroll
        for (int ww = 0; ww < 7; ww++) v += red[ww * 4 + tid];
        atomicAdd(&g_acc[c * 4 + tid], v);
    }
}

__global__ void k_stats(const float* __restrict__ gL, const float* __restrict__ bL,
                        const float* __restrict__ gS, const float* __restrict__ bS) {
    int c = blockIdx.x * blockDim.x + threadIdx.x;
    if (c >= C_) return;
    const float inv_n = 1.f / (float)NHW_;
    float mL = g_acc[c*4+0] * inv_n;
    float vL = g_acc[c*4+1] * inv_n - mL * mL;
    float aL = gL[c] * rsqrtf(vL + 1e-5f);
    float mS = g_acc[c*4+2] * inv_n;
    float vS = g_acc[c*4+3] * inv_n - mS * mS;
    float aS = gS[c] * rsqrtf(vS + 1e-5f);
    g_prm[c]        = aL;
    g_prm[C_ + c]   = aS;
    g_prm[2*C_ + c] = bL[c] - mL * aL + bS[c] - mS * aS;
}

__global__ __launch_bounds__(256) void k_out(float* __restrict__ out) {
    int i = blockIdx.x * blockDim.x + threadIdx.x;
    if (i >= TOT_ / 4) return;
    int e = i * 4;
    int c = (e / HW_) % C_;          // HW_ divisible by 4 -> channel constant in float4
    float aL = g_prm[c], aS = g_prm[C_ + c], bb = g_prm[2*C_ + c];
    float4 l = ((const float4*)g_yl)[i];
    float4 s = ((const float4*)g_ys)[i];
    float4 o;
    o.x = fmaf(aL, l.x, fmaf(aS, s.x, bb));
    o.y = fmaf(aL, l.y, fmaf(aS, s.y, bb));
    o.z = fmaf(aL, l.z, fmaf(aS, s.z, bb));
    o.w = fmaf(aL, l.w, fmaf(aS, s.w, bb));
    ((float4*)out)[i] = o;
}

extern "C" void kernel_launch(void* const* d_in, const int* in_sizes, int n_in,
                              void* d_out, int out_size) {
    const float* x  = (const float*)d_in[0];
    const float* wl = (const float*)d_in[1];
    const float* gl = (const float*)d_in[2];
    const float* bl = (const float*)d_in[3];
    const float* ws = (const float*)d_in[4];
    const float* gs = (const float*)d_in[5];
    const float* bs = (const float*)d_in[6];

    k_zero<<<6, 256>>>();
    k_conv<<<B_ * C_, NTHR>>>(x, wl, ws);
    k_stats<<<2, 192>>>(gl, bl, gs, bs);
    k_out<<<(TOT_ / 4 + 255) / 256, 256>>>((float*)d_out);
}

// round 9
// speedup vs baseline: 1.1287x; 1.0355x over previous
#include <cuda_runtime.h>

#define B_   16
#define C_   384
#define H_   56
#define W_   56
#define HW_  3136
#define NHW_ 50176
#define TOT_ 19267584
#define KL   31
#define PL   15
#define KS   5
#define TS   86        // 56 + 2*15
#define STR  87        // odd stride: consecutive rows -> distinct banks
#define WIDE 14        // output columns per thread
#define NTHR 224       // 56 rows x 4 strips -- every lane works
#define TILE_PAD 7488  // TS*STR = 7482, padded to multiple of 4

// Scratch (allocation-free contract: __device__ globals)
__device__ float g_yl[TOT_];
__device__ float g_ys[TOT_];
__device__ float g_acc[C_ * 4];   // per channel: sumL, sqL, sumS, sqS
__device__ float g_prm[C_ * 3];   // per channel: aL, aS, bias

__global__ void k_zero() {
    int i = blockIdx.x * blockDim.x + threadIdx.x;
    if (i < C_ * 4) g_acc[i] = 0.f;
}

__global__ __launch_bounds__(NTHR) void k_conv(const float* __restrict__ x,
                                               const float* __restrict__ wl_g,
                                               const float* __restrict__ ws_g) {
    __shared__ __align__(16) float tile[TILE_PAD];
    __shared__ __align__(16) float wlp[KL * 32];   // weight rows padded to 32
    __shared__ float ws[32];
    __shared__ float red[7 * 4];

    const int blk = blockIdx.x;          // n*C + c
    const int c   = blk % C_;
    const int tid = threadIdx.x;
    const float* img = x + (size_t)blk * HW_;

    const int row   = tid % 56;          // output row / interior row
    const int strip = tid / 56;          // 0..3
    const int col0  = strip * WIDE;      // 0, 14, 28, 42

    // ---- phase 1: zero full padded tile (float4), load weights ----
    #pragma unroll
    for (int u = 0; u < TILE_PAD / 4; u += NTHR) {
        int idx = u + tid;
        if (idx < TILE_PAD / 4) ((float4*)tile)[idx] = make_float4(0.f, 0.f, 0.f, 0.f);
    }
    for (int idx = tid; idx < KL * 32; idx += NTHR) {
        int i = idx >> 5, j = idx & 31;
        wlp[idx] = (j < KL) ? wl_g[c * KL * KL + i * KL + j] : 0.f;
    }
    if (tid < KS * KS) ws[tid] = ws_g[c * KS * KS + tid];
    __syncthreads();

    // ---- phase 2: interior load, exact fit: thread = (row, 14-col strip) ----
    {
        const float* src = img + row * W_ + col0;   // row*56 + strip*14 is even -> 8B aligned
        float* dst = &tile[(row + PL) * STR + PL + col0];
        #pragma unroll
        for (int t = 0; t < WIDE; t += 2) {
            float2 v = *(const float2*)&src[t];
            dst[t]     = v.x;
            dst[t + 1] = v.y;
        }
    }
    __syncthreads();

    const size_t ob = (size_t)blk * HW_ + (size_t)row * W_ + col0;
    float sL = 0.f, qL = 0.f, sS = 0.f, qS = 0.f;

    // ---- 31x31 depthwise conv: weights hoisted to registers per kernel row ----
    {
        float accL[WIDE];
        #pragma unroll
        for (int t = 0; t < WIDE; t++) accL[t] = 0.f;

        #pragma unroll 1
        for (int i = 0; i < KL; i++) {
            const float* xr = &tile[(row + i) * STR + col0];

            float wreg[32];
            {
                const float4* wrow = (const float4*)&wlp[i * 32];
                #pragma unroll
                for (int u = 0; u < 8; u++) {
                    float4 t4 = wrow[u];
                    wreg[4*u]   = t4.x; wreg[4*u+1] = t4.y;
                    wreg[4*u+2] = t4.z; wreg[4*u+3] = t4.w;
                }
            }

            float xw[WIDE];
            #pragma unroll
            for (int t = 0; t < WIDE; t++) xw[t] = xr[t];
            #pragma unroll
            for (int j = 0; j < KL; j++) {
                const float wv = wreg[j];
                #pragma unroll
                for (int t = 0; t < WIDE; t++)
                    accL[t] = fmaf(xw[(j + t) % WIDE], wv, accL[t]);
                if (j < KL - 1) xw[j % WIDE] = xr[j + WIDE];
            }
        }

        #pragma unroll
        for (int t = 0; t < WIDE; t += 2)
            *(float2*)&g_yl[ob + t] = make_float2(accL[t], accL[t+1]);
        #pragma unroll
        for (int t = 0; t < WIDE; t++) {
            sL += accL[t]; qL = fmaf(accL[t], accL[t], qL);
        }
    }

    // ---- 5x5 depthwise conv (pad 2): offset +13; weights in registers ----
    {
        float wsr[KS * KS];
        #pragma unroll
        for (int k = 0; k < KS * KS; k++) wsr[k] = ws[k];

        float accS[WIDE];
        #pragma unroll
        for (int t = 0; t < WIDE; t++) accS[t] = 0.f;
        #pragma unroll 1
        for (int i = 0; i < KS; i++) {
            const float* xr = &tile[(row + i + 13) * STR + col0 + 13];
            float xv[WIDE + 4];
            #pragma unroll
            for (int t = 0; t < WIDE + 4; t++) xv[t] = xr[t];
            #pragma unroll
            for (int j = 0; j < KS; j++) {
                const float wv = wsr[i * KS + j];
                #pragma unroll
                for (int t = 0; t < WIDE; t++)
                    accS[t] = fmaf(xv[j + t], wv, accS[t]);
            }
        }

        #pragma unroll
        for (int t = 0; t < WIDE; t += 2)
            *(float2*)&g_ys[ob + t] = make_float2(accS[t], accS[t+1]);
        #pragma unroll
        for (int t = 0; t < WIDE; t++) {
            sS += accS[t]; qS = fmaf(accS[t], accS[t], qS);
        }
    }

    // ---- block reduction of the 4 stats (7 warps) ----
    #pragma unroll
    for (int o = 16; o; o >>= 1) {
        sL += __shfl_down_sync(0xffffffffu, sL, o);
        qL += __shfl_down_sync(0xffffffffu, qL, o);
        sS += __shfl_down_sync(0xffffffffu, sS, o);
        qS += __shfl_down_sync(0xffffffffu, qS, o);
    }
    const int lane = tid & 31, wpid = tid >> 5;
    if (lane == 0) { red[wpid*4+0]=sL; red[wpid*4+1]=qL; red[wpid*4+2]=sS; red[wpid*4+3]=qS; }
    __syncthreads();
    if (tid < 4) {
        float v = 0.f;
        #pragma unroll
        for (int ww = 0; ww < 7; ww++) v += red[ww * 4 + tid];
        atomicAdd(&g_acc[c * 4 + tid], v);
    }
}

__global__ void k_stats(const float* __restrict__ gL, const float* __restrict__ bL,
                        const float* __restrict__ gS, const float* __restrict__ bS) {
    int c = blockIdx.x * blockDim.x + threadIdx.x;
    if (c >= C_) return;
    const float inv_n = 1.f / (float)NHW_;
    float mL = g_acc[c*4+0] * inv_n;
    float vL = g_acc[c*4+1] * inv_n - mL * mL;
    float aL = gL[c] * rsqrtf(vL + 1e-5f);
    float mS = g_acc[c*4+2] * inv_n;
    float vS = g_acc[c*4+3] * inv_n - mS * mS;
    float aS = gS[c] * rsqrtf(vS + 1e-5f);
    g_prm[c]        = aL;
    g_prm[C_ + c]   = aS;
    g_prm[2*C_ + c] = bL[c] - mL * aL + bS[c] - mS * aS;
}

__global__ __launch_bounds__(256) void k_out(float* __restrict__ out) {
    int i = blockIdx.x * blockDim.x + threadIdx.x;
    if (i >= TOT_ / 4) return;
    int e = i * 4;
    int c = (e / HW_) % C_;          // HW_ divisible by 4 -> channel constant in float4
    float aL = g_prm[c], aS = g_prm[C_ + c], bb = g_prm[2*C_ + c];
    float4 l = ((const float4*)g_yl)[i];
    float4 s = ((const float4*)g_ys)[i];
    float4 o;
    o.x = fmaf(aL, l.x, fmaf(aS, s.x, bb));
    o.y = fmaf(aL, l.y, fmaf(aS, s.y, bb));
    o.z = fmaf(aL, l.z, fmaf(aS, s.z, bb));
    o.w = fmaf(aL, l.w, fmaf(aS, s.w, bb));
    ((float4*)out)[i] = o;
}

extern "C" void kernel_launch(void* const* d_in, const int* in_sizes, int n_in,
                              void* d_out, int out_size) {
    const float* x  = (const float*)d_in[0];
    const float* wl = (const float*)d_in[1];
    const float* gl = (const float*)d_in[2];
    const float* bl = (const float*)d_in[3];
    const float* ws = (const float*)d_in[4];
    const float* gs = (const float*)d_in[5];
    const float* bs = (const float*)d_in[6];

    k_zero<<<6, 256>>>();
    k_conv<<<B_ * C_, NTHR>>>(x, wl, ws);
    k_stats<<<2, 192>>>(gl, bl, gs, bs);
    k_out<<<(TOT_ / 4 + 255) / 256, 256>>>((float*)d_out);
}

// round 10
// speedup vs baseline: 1.1334x; 1.0042x over previous
#include <cuda_runtime.h>

#define B_   16
#define C_   384
#define H_   56
#define W_   56
#define HW_  3136
#define NHW_ 50176
#define TOT_ 19267584
#define KL   31
#define PL   15
#define KS   5
#define TS   86        // 56 + 2*15
#define STR  90        // even stride, gcd(90,32)=2 -> conflict-free float2 rows
#define WIDE 14        // output columns per thread
#define NTHR 224       // 56 rows x 4 strips -- every lane works
#define TILE_PAD (TS * STR)   // 7740, multiple of 4

// Scratch (allocation-free contract: __device__ globals)
__device__ float g_yl[TOT_];
__device__ float g_ys[TOT_];
__device__ float g_acc[C_ * 4];   // per channel: sumL, sqL, sumS, sqS
__device__ float g_prm[C_ * 3];   // per channel: aL, aS, bias

__global__ void k_zero() {
    int i = blockIdx.x * blockDim.x + threadIdx.x;
    if (i < C_ * 4) g_acc[i] = 0.f;
}

__global__ __launch_bounds__(NTHR) void k_conv(const float* __restrict__ x,
                                               const float* __restrict__ wl_g,
                                               const float* __restrict__ ws_g) {
    __shared__ __align__(16) float tile[TILE_PAD];
    __shared__ __align__(16) float wlp[KL * 32];   // weight rows padded to 32
    __shared__ float ws[32];
    __shared__ float red[7 * 4];

    const int blk = blockIdx.x;          // n*C + c
    const int c   = blk % C_;
    const int tid = threadIdx.x;
    const float* img = x + (size_t)blk * HW_;

    const int row   = tid % 56;          // output row / interior row
    const int strip = tid / 56;          // 0..3
    const int col0  = strip * WIDE;      // 0, 14, 28, 42 (all even)

    // ---- phase 1: zero full padded tile (float4), load weights ----
    #pragma unroll
    for (int u = 0; u < TILE_PAD / 4; u += NTHR) {
        int idx = u + tid;
        if (idx < TILE_PAD / 4) ((float4*)tile)[idx] = make_float4(0.f, 0.f, 0.f, 0.f);
    }
    for (int idx = tid; idx < KL * 32; idx += NTHR) {
        int i = idx >> 5, j = idx & 31;
        wlp[idx] = (j < KL) ? wl_g[c * KL * KL + i * KL + j] : 0.f;
    }
    if (tid < KS * KS) ws[tid] = ws_g[c * KS * KS + tid];
    __syncthreads();

    // ---- phase 2: interior load, exact fit: thread = (row, 14-col strip) ----
    {
        const float* src = img + row * W_ + col0;   // even offset -> 8B aligned
        float* dst = &tile[(row + PL) * STR + PL + col0];
        #pragma unroll
        for (int t = 0; t < WIDE; t += 2) {
            float2 v = *(const float2*)&src[t];
            dst[t]     = v.x;
            dst[t + 1] = v.y;
        }
    }
    __syncthreads();

    const size_t ob = (size_t)blk * HW_ + (size_t)row * W_ + col0;
    float sL = 0.f, qL = 0.f, sS = 0.f, qS = 0.f;

    // ---- 31x31 depthwise conv: reg weights + 16-slot float2-fed window ----
    {
        float accL[WIDE];
        #pragma unroll
        for (int t = 0; t < WIDE; t++) accL[t] = 0.f;

        #pragma unroll 1
        for (int i = 0; i < KL; i++) {
            const float* xr = &tile[(row + i) * STR + col0];   // even base

            float wreg[32];
            {
                const float4* wrow = (const float4*)&wlp[i * 32];
                #pragma unroll
                for (int u = 0; u < 8; u++) {
                    float4 t4 = wrow[u];
                    wreg[4*u]   = t4.x; wreg[4*u+1] = t4.y;
                    wreg[4*u+2] = t4.z; wreg[4*u+3] = t4.w;
                }
            }

            float xw[16];
            #pragma unroll
            for (int u = 0; u < 8; u++) {
                float2 v = *(const float2*)&xr[2 * u];
                xw[2*u] = v.x; xw[2*u+1] = v.y;
            }

            #pragma unroll
            for (int j = 0; j < KL; j++) {
                const float wv = wreg[j];
                #pragma unroll
                for (int t = 0; t < WIDE; t++)
                    accL[t] = fmaf(xw[(j + t) & 15], wv, accL[t]);
                if ((j & 1) && j <= 27) {        // paired refill, even address
                    float2 v = *(const float2*)&xr[j + 15];
                    xw[(j + 15) & 15] = v.x;
                    xw[(j + 16) & 15] = v.y;
                }
            }
        }

        #pragma unroll
        for (int t = 0; t < WIDE; t += 2)
            *(float2*)&g_yl[ob + t] = make_float2(accL[t], accL[t+1]);
        #pragma unroll
        for (int t = 0; t < WIDE; t++) {
            sL += accL[t]; qL = fmaf(accL[t], accL[t], qL);
        }
    }

    // ---- 5x5 depthwise conv (pad 2): even base at col0+12, reg weights ----
    {
        float wsr[KS * KS];
        #pragma unroll
        for (int k = 0; k < KS * KS; k++) wsr[k] = ws[k];

        float accS[WIDE];
        #pragma unroll
        for (int t = 0; t < WIDE; t++) accS[t] = 0.f;
        #pragma unroll 1
        for (int i = 0; i < KS; i++) {
            const float* xr = &tile[(row + i + 13) * STR + col0 + 12];  // even base
            float xv[20];
            #pragma unroll
            for (int u = 0; u < 10; u++) {
                float2 v = *(const float2*)&xr[2 * u];
                xv[2*u] = v.x; xv[2*u+1] = v.y;
            }
            #pragma unroll
            for (int j = 0; j < KS; j++) {
                const float wv = wsr[i * KS + j];
                #pragma unroll
                for (int t = 0; t < WIDE; t++)
                    accS[t] = fmaf(xv[1 + j + t], wv, accS[t]);
            }
        }

        #pragma unroll
        for (int t = 0; t < WIDE; t += 2)
            *(float2*)&g_ys[ob + t] = make_float2(accS[t], accS[t+1]);
        #pragma unroll
        for (int t = 0; t < WIDE; t++) {
            sS += accS[t]; qS = fmaf(accS[t], accS[t], qS);
        }
    }

    // ---- block reduction of the 4 stats (7 warps) ----
    #pragma unroll
    for (int o = 16; o; o >>= 1) {
        sL += __shfl_down_sync(0xffffffffu, sL, o);
        qL += __shfl_down_sync(0xffffffffu, qL, o);
        sS += __shfl_down_sync(0xffffffffu, sS, o);
        qS += __shfl_down_sync(0xffffffffu, qS, o);
    }
    const int lane = tid & 31, wpid = tid >> 5;
    if (lane == 0) { red[wpid*4+0]=sL; red[wpid*4+1]=qL; red[wpid*4+2]=sS; red[wpid*4+3]=qS; }
    __syncthreads();
    if (tid < 4) {
        float v = 0.f;
        #pragma unroll
        for (int ww = 0; ww < 7; ww++) v += red[ww * 4 + tid];
        atomicAdd(&g_acc[c * 4 + tid], v);
    }
}

__global__ void k_stats(const float* __restrict__ gL, const float* __restrict__ bL,
                        const float* __restrict__ gS, const float* __restrict__ bS) {
    int c = blockIdx.x * blockDim.x + threadIdx.x;
    if (c >= C_) return;
    const float inv_n = 1.f / (float)NHW_;
    float mL = g_acc[c*4+0] * inv_n;
    float vL = g_acc[c*4+1] * inv_n - mL * mL;
    float aL = gL[c] * rsqrtf(vL + 1e-5f);
    float mS = g_acc[c*4+2] * inv_n;
    float vS = g_acc[c*4+3] * inv_n - mS * mS;
    float aS = gS[c] * rsqrtf(vS + 1e-5f);
    g_prm[c]        = aL;
    g_prm[C_ + c]   = aS;
    g_prm[2*C_ + c] = bL[c] - mL * aL + bS[c] - mS * aS;
}

__global__ __launch_bounds__(256) void k_out(float* __restrict__ out) {
    int i = blockIdx.x * blockDim.x + threadIdx.x;
    if (i >= TOT_ / 4) return;
    int e = i * 4;
    int c = (e / HW_) % C_;          // HW_ divisible by 4 -> channel constant in float4
    float aL = g_prm[c], aS = g_prm[C_ + c], bb = g_prm[2*C_ + c];
    float4 l = ((const float4*)g_yl)[i];
    float4 s = ((const float4*)g_ys)[i];
    float4 o;
    o.x = fmaf(aL, l.x, fmaf(aS, s.x, bb));
    o.y = fmaf(aL, l.y, fmaf(aS, s.y, bb));
    o.z = fmaf(aL, l.z, fmaf(aS, s.z, bb));
    o.w = fmaf(aL, l.w, fmaf(aS, s.w, bb));
    ((float4*)out)[i] = o;
}

extern "C" void kernel_launch(void* const* d_in, const int* in_sizes, int n_in,
                              void* d_out, int out_size) {
    const float* x  = (const float*)d_in[0];
    const float* wl = (const float*)d_in[1];
    const float* gl = (const float*)d_in[2];
    const float* bl = (const float*)d_in[3];
    const float* ws = (const float*)d_in[4];
    const float* gs = (const float*)d_in[5];
    const float* bs = (const float*)d_in[6];

    k_zero<<<6, 256>>>();
    k_conv<<<B_ * C_, NTHR>>>(x, wl, ws);
    k_stats<<<2, 192>>>(gl, bl, gs, bs);
    k_out<<<(TOT_ / 4 + 255) / 256, 256>>>((float*)d_out);
}

// round 11
// speedup vs baseline: 1.2355x; 1.0901x over previous
#include <cuda_runtime.h>

#define B_   16
#define C_   384
#define H_   56
#define W_   56
#define HW_  3136
#define NHW_ 50176
#define TOT_ 19267584
#define KL   31
#define PL   15
#define KS   5
#define TS   86        // 56 + 2*15
#define STR  90        // even stride, gcd(90,32)=2 -> conflict-free float2 rows
#define WIDE 14        // output columns per thread
#define NTHR 224       // 56 rows x 4 strips -- every lane works
#define TILE_PAD (TS * STR)   // 7740, multiple of 4

// Scratch (allocation-free contract: __device__ globals)
__device__ float g_yl[TOT_];
__device__ float g_ys[TOT_];
__device__ float g_acc[C_ * 4];   // per channel: sumL, sqL, sumS, sqS
__device__ float g_prm[C_ * 3];   // per channel: aL, aS, bias

__global__ void k_zero() {
    int i = blockIdx.x * blockDim.x + threadIdx.x;
    if (i < C_ * 4) g_acc[i] = 0.f;
}

__global__ __launch_bounds__(NTHR, 4) void k_conv(const float* __restrict__ x,
                                                  const float* __restrict__ wl_g,
                                                  const float* __restrict__ ws_g) {
    __shared__ __align__(16) float tile[TILE_PAD];
    __shared__ __align__(16) float wlp[KL * 32];   // weight rows padded to 32
    __shared__ float ws[32];
    __shared__ float red[7 * 4];

    const int blk = blockIdx.x;          // n*C + c
    const int c   = blk % C_;
    const int tid = threadIdx.x;
    const float* img = x + (size_t)blk * HW_;

    const int row   = tid % 56;          // output row / interior row
    const int strip = tid / 56;          // 0..3
    const int col0  = strip * WIDE;      // 0, 14, 28, 42 (all even)

    // ---- phase 1: zero full padded tile (float4), load weights ----
    #pragma unroll
    for (int u = 0; u < TILE_PAD / 4; u += NTHR) {
        int idx = u + tid;
        if (idx < TILE_PAD / 4) ((float4*)tile)[idx] = make_float4(0.f, 0.f, 0.f, 0.f);
    }
    for (int idx = tid; idx < KL * 32; idx += NTHR) {
        int i = idx >> 5, j = idx & 31;
        wlp[idx] = (j < KL) ? wl_g[c * KL * KL + i * KL + j] : 0.f;
    }
    if (tid < KS * KS) ws[tid] = ws_g[c * KS * KS + tid];
    __syncthreads();

    // ---- phase 2: interior load, exact fit: thread = (row, 14-col strip) ----
    {
        const float* src = img + row * W_ + col0;   // even offset -> 8B aligned
        float* dst = &tile[(row + PL) * STR + PL + col0];
        #pragma unroll
        for (int t = 0; t < WIDE; t += 2) {
            float2 v = *(const float2*)&src[t];
            dst[t]     = v.x;
            dst[t + 1] = v.y;
        }
    }
    __syncthreads();

    const size_t ob = (size_t)blk * HW_ + (size_t)row * W_ + col0;
    float sL = 0.f, qL = 0.f, sS = 0.f, qS = 0.f;

    // ---- 31x31 depthwise conv: JIT half-hoisted weights + 16-slot window ----
    {
        float accL[WIDE];
        #pragma unroll
        for (int t = 0; t < WIDE; t++) accL[t] = 0.f;

        #pragma unroll 1
        for (int i = 0; i < KL; i++) {
            const float* xr = &tile[(row + i) * STR + col0];   // even base
            const float4* wrow = (const float4*)&wlp[i * 32];

            // first weight half (taps 0..15)
            float wregA[16];
            #pragma unroll
            for (int u = 0; u < 4; u++) {
                float4 t4 = wrow[u];
                wregA[4*u]   = t4.x; wregA[4*u+1] = t4.y;
                wregA[4*u+2] = t4.z; wregA[4*u+3] = t4.w;
            }

            float xw[16];
            #pragma unroll
            for (int u = 0; u < 8; u++) {
                float2 v = *(const float2*)&xr[2 * u];
                xw[2*u] = v.x; xw[2*u+1] = v.y;
            }

            #pragma unroll
            for (int j = 0; j < 12; j++) {
                const float wv = wregA[j];
                #pragma unroll
                for (int t = 0; t < WIDE; t++)
                    accL[t] = fmaf(xw[(j + t) & 15], wv, accL[t]);
                if (j & 1) {                      // paired refill, even address
                    float2 v = *(const float2*)&xr[j + 15];
                    xw[(j + 15) & 15] = v.x;
                    xw[(j + 16) & 15] = v.y;
                }
            }

            // second weight half (taps 16..30), loaded 4 taps early for latency
            float wregB[16];
            #pragma unroll
            for (int u = 0; u < 4; u++) {
                float4 t4 = wrow[4 + u];
                wregB[4*u]   = t4.x; wregB[4*u+1] = t4.y;
                wregB[4*u+2] = t4.z; wregB[4*u+3] = t4.w;
            }

            #pragma unroll
            for (int j = 12; j < 16; j++) {
                const float wv = wregA[j];
                #pragma unroll
                for (int t = 0; t < WIDE; t++)
                    accL[t] = fmaf(xw[(j + t) & 15], wv, accL[t]);
                if (j & 1) {
                    float2 v = *(const float2*)&xr[j + 15];
                    xw[(j + 15) & 15] = v.x;
                    xw[(j + 16) & 15] = v.y;
                }
            }

            #pragma unroll
            for (int j = 16; j < KL; j++) {
                const float wv = wregB[j - 16];
                #pragma unroll
                for (int t = 0; t < WIDE; t++)
                    accL[t] = fmaf(xw[(j + t) & 15], wv, accL[t]);
                if ((j & 1) && j <= 27) {
                    float2 v = *(const float2*)&xr[j + 15];
                    xw[(j + 15) & 15] = v.x;
                    xw[(j + 16) & 15] = v.y;
                }
            }
        }

        #pragma unroll
        for (int t = 0; t < WIDE; t += 2)
            *(float2*)&g_yl[ob + t] = make_float2(accL[t], accL[t+1]);
        #pragma unroll
        for (int t = 0; t < WIDE; t++) {
            sL += accL[t]; qL = fmaf(accL[t], accL[t], qL);
        }
    }

    // ---- 5x5 depthwise conv (pad 2): even base at col0+12, per-row weights ----
    {
        float accS[WIDE];
        #pragma unroll
        for (int t = 0; t < WIDE; t++) accS[t] = 0.f;
        #pragma unroll 1
        for (int i = 0; i < KS; i++) {
            const float* xr = &tile[(row + i + 13) * STR + col0 + 12];  // even base
            float wsr[KS];
            #pragma unroll
            for (int k = 0; k < KS; k++) wsr[k] = ws[i * KS + k];
            float xv[20];
            #pragma unroll
            for (int u = 0; u < 10; u++) {
                float2 v = *(const float2*)&xr[2 * u];
                xv[2*u] = v.x; xv[2*u+1] = v.y;
            }
            #pragma unroll
            for (int j = 0; j < KS; j++) {
                const float wv = wsr[j];
                #pragma unroll
                for (int t = 0; t < WIDE; t++)
                    accS[t] = fmaf(xv[1 + j + t], wv, accS[t]);
            }
        }

        #pragma unroll
        for (int t = 0; t < WIDE; t += 2)
            *(float2*)&g_ys[ob + t] = make_float2(accS[t], accS[t+1]);
        #pragma unroll
        for (int t = 0; t < WIDE; t++) {
            sS += accS[t]; qS = fmaf(accS[t], accS[t], qS);
        }
    }

    // ---- block reduction of the 4 stats (7 warps) ----
    #pragma unroll
    for (int o = 16; o; o >>= 1) {
        sL += __shfl_down_sync(0xffffffffu, sL, o);
        qL += __shfl_down_sync(0xffffffffu, qL, o);
        sS += __shfl_down_sync(0xffffffffu, sS, o);
        qS += __shfl_down_sync(0xffffffffu, qS, o);
    }
    const int lane = tid & 31, wpid = tid >> 5;
    if (lane == 0) { red[wpid*4+0]=sL; red[wpid*4+1]=qL; red[wpid*4+2]=sS; red[wpid*4+3]=qS; }
    __syncthreads();
    if (tid < 4) {
        float v = 0.f;
        #pragma unroll
        for (int ww = 0; ww < 7; ww++) v += red[ww * 4 + tid];
        atomicAdd(&g_acc[c * 4 + tid], v);
    }
}

__global__ void k_stats(const float* __restrict__ gL, const float* __restrict__ bL,
                        const float* __restrict__ gS, const float* __restrict__ bS) {
    int c = blockIdx.x * blockDim.x + threadIdx.x;
    if (c >= C_) return;
    const float inv_n = 1.f / (float)NHW_;
    float mL = g_acc[c*4+0] * inv_n;
    float vL = g_acc[c*4+1] * inv_n - mL * mL;
    float aL = gL[c] * rsqrtf(vL + 1e-5f);
    float mS = g_acc[c*4+2] * inv_n;
    float vS = g_acc[c*4+3] * inv_n - mS * mS;
    float aS = gS[c] * rsqrtf(vS + 1e-5f);
    g_prm[c]        = aL;
    g_prm[C_ + c]   = aS;
    g_prm[2*C_ + c] = bL[c] - mL * aL + bS[c] - mS * aS;
}

__global__ __launch_bounds__(256) void k_out(float* __restrict__ out) {
    int i = blockIdx.x * blockDim.x + threadIdx.x;
    if (i >= TOT_ / 4) return;
    int e = i * 4;
    int c = (e / HW_) % C_;          // HW_ divisible by 4 -> channel constant in float4
    float aL = g_prm[c], aS = g_prm[C_ + c], bb = g_prm[2*C_ + c];
    float4 l = ((const float4*)g_yl)[i];
    float4 s = ((const float4*)g_ys)[i];
    float4 o;
    o.x = fmaf(aL, l.x, fmaf(aS, s.x, bb));
    o.y = fmaf(aL, l.y, fmaf(aS, s.y, bb));
    o.z = fmaf(aL, l.z, fmaf(aS, s.z, bb));
    o.w = fmaf(aL, l.w, fmaf(aS, s.w, bb));
    ((float4*)out)[i] = o;
}

extern "C" void kernel_launch(void* const* d_in, const int* in_sizes, int n_in,
                              void* d_out, int out_size) {
    const float* x  = (const float*)d_in[0];
    const float* wl = (const float*)d_in[1];
    const float* gl = (const float*)d_in[2];
    const float* bl = (const float*)d_in[3];
    const float* ws = (const float*)d_in[4];
    const float* gs = (const float*)d_in[5];
    const float* bs = (const float*)d_in[6];

    k_zero<<<6, 256>>>();
    k_conv<<<B_ * C_, NTHR>>>(x, wl, ws);
    k_stats<<<2, 192>>>(gl, bl, gs, bs);
    k_out<<<(TOT_ / 4 + 255) / 256, 256>>>((float*)d_out);
}